// round 10
// baseline (speedup 1.0000x reference)
#include <cuda_runtime.h>
#include <cuda_bf16.h>
#include <cstdint>

#define N_ 16384
#define T_ 60
#define M_ 8
#define LOG_2PI 1.8378770664093453f

#define BLK 256
#define UNROLL 4
#define ITEMS (N_ * T_)                 // 983040
#define IPB ((BLK / M_) * UNROLL)       // 128 items per block
#define GRID (ITEMS / IPB)              // 7680 (exact)
#define NSLOT 128

// Device-global scratch (zero-init at load; self-reset by the final block).
__device__ float g_accn[T_ * NSLOT];
__device__ float g_accd[T_ * NSLOT];
__device__ unsigned int g_ticket;

// 3 blocks/SM cap -> up to ~85 regs/thread: room to keep all batched loads in flight.
__global__ __launch_bounds__(BLK, 3) void nll_fused_kernel(
    const float* __restrict__ mu,
    const float* __restrict__ sigma,
    const float* __restrict__ pi,
    const float* __restrict__ x,
    const float* __restrict__ mask,
    float* __restrict__ out)
{
    __shared__ float s_num[T_];
    __shared__ float s_den[T_];
    __shared__ unsigned int s_last;

    const int tid = threadIdx.x;
    const int g   = tid >> 3;           // item group within block (0..31)
    const int m   = tid & 7;            // mixture component (0..7)
    const int base = blockIdx.x * IPB;

    if (tid < T_) { s_num[tid] = 0.0f; s_den[tid] = 0.0f; }
    __syncthreads();

    const float4* sg4 = reinterpret_cast<const float4*>(sigma);
    const float2* mu2 = reinterpret_cast<const float2*>(mu);
    const float2* x2  = reinterpret_cast<const float2*>(x);

    // ---------------- Phase 1: batch ALL loads (max MLP, no dependent compute) ----
    float4 sv[UNROLL];
    float2 mv[UNROLL];
    float2 xv[UNROLL];
    float  pv[UNROLL];
    float  mk[UNROLL];
    int    nn[UNROLL], tt[UNROLL];

    #pragma unroll
    for (int it = 0; it < UNROLL; it++) {
        const int item = base + it * 32 + g;      // item = n*T + t
        nn[it] = item / T_;
        tt[it] = item - nn[it] * T_;
        sv[it] = __ldcs(sg4 + (size_t)item * M_ + m);   // streaming: no reuse
        mv[it] = __ldcs(mu2 + (size_t)item * M_ + m);
        xv[it] = __ldg (x2  + item);                    // group broadcast
        pv[it] = __ldg (pi  + (size_t)nn[it] * M_ + m); // reused across t -> cache
        mk[it] = __ldcs(mask + item);                   // group broadcast
    }

    // ---------------- Phase 2: compute ----------------
    #pragma unroll
    for (int it = 0; it < UNROLL; it++) {
        float4 s = sv[it];
        float d0 = xv[it].x - mv[it].x;
        float d1 = xv[it].y - mv[it].y;
        float det  = fmaf(s.x, s.w, -s.y * s.z);
        float quad = fmaf(d0 * d0, s.w, fmaf(-2.0f * s.y, d0 * d1, d1 * d1 * s.x));
        float lp   = fmaf(-0.5f, quad * __frcp_rn(det),
                          fmaf(-0.5f, __logf(det), -LOG_2PI));

        // 8-lane logsumexp over components (bfly shuffles stay in the group)
        float a  = lp + pv[it];
        float mx = a;
        mx = fmaxf(mx, __shfl_xor_sync(0xFFFFFFFFu, mx, 1));
        mx = fmaxf(mx, __shfl_xor_sync(0xFFFFFFFFu, mx, 2));
        mx = fmaxf(mx, __shfl_xor_sync(0xFFFFFFFFu, mx, 4));
        float ea = __expf(a - mx);
        float ep = __expf(pv[it]);       // |pi| small: no max shift needed
        ea += __shfl_xor_sync(0xFFFFFFFFu, ea, 1);
        ep += __shfl_xor_sync(0xFFFFFFFFu, ep, 1);
        ea += __shfl_xor_sync(0xFFFFFFFFu, ea, 2);
        ep += __shfl_xor_sync(0xFFFFFFFFu, ep, 2);
        ea += __shfl_xor_sync(0xFFFFFFFFu, ea, 4);
        ep += __shfl_xor_sync(0xFFFFFFFFu, ep, 4);

        if (m == 0) {
            float loss = -(mx + __logf(ea) - __logf(ep));
            atomicAdd(&s_num[tt[it]], loss * mk[it]);
            atomicAdd(&s_den[tt[it]], mk[it]);
        }
    }
    __syncthreads();

    // ---- Spread global accumulation (GRID/NSLOT = 60 blocks per address) ----
    const int slot = blockIdx.x & (NSLOT - 1);
    if (tid < T_) {
        atomicAdd(&g_accn[tid * NSLOT + slot], s_num[tid]);
        atomicAdd(&g_accd[tid * NSLOT + slot], s_den[tid]);
    }

    // ---- Last-block finalize (ticket), then self-reset for replay ----
    __threadfence();
    if (tid == 0) s_last = atomicAdd(&g_ticket, 1u);
    __syncthreads();

    if (s_last == (unsigned int)(gridDim.x - 1)) {
        __threadfence();
        double v = 0.0;
        if (tid < T_) {
            const float4* pn = reinterpret_cast<const float4*>(g_accn + tid * NSLOT);
            const float4* pd = reinterpret_cast<const float4*>(g_accd + tid * NSLOT);
            double num = 0.0, den = 0.0;
            #pragma unroll 8
            for (int j = 0; j < NSLOT / 4; j++) {
                float4 a = pn[j];
                float4 b = pd[j];
                num += (double)a.x + (double)a.y + (double)a.z + (double)a.w;
                den += (double)b.x + (double)b.y + (double)b.z + (double)b.w;
            }
            v = num / den;
        }
        #pragma unroll
        for (int off = 16; off > 0; off >>= 1)
            v += __shfl_down_sync(0xFFFFFFFFu, v, off);
        __shared__ double partial[2];
        if (tid == 0)  partial[0] = v;
        if (tid == 32) partial[1] = v;
        __syncthreads();
        if (tid == 0) out[0] = (float)(partial[0] + partial[1]);
        for (int i = tid; i < T_ * NSLOT; i += BLK) {
            g_accn[i] = 0.0f;
            g_accd[i] = 0.0f;
        }
        if (tid == 0) g_ticket = 0u;
    }
}

extern "C" void kernel_launch(void* const* d_in, const int* in_sizes, int n_in,
                              void* d_out, int out_size) {
    const float* mu    = (const float*)d_in[0];
    const float* sigma = (const float*)d_in[1];
    const float* pi    = (const float*)d_in[2];
    const float* x     = (const float*)d_in[3];
    const float* mask  = (const float*)d_in[4];
    float* out = (float*)d_out;

    nll_fused_kernel<<<GRID, BLK>>>(mu, sigma, pi, x, mask, out);
}

// round 11
// speedup vs baseline: 1.3653x; 1.3653x over previous
#include <cuda_runtime.h>
#include <cstdint>

#define N_ 16384
#define T_ 60
#define M_ 8
#define LOG_2PI 1.8378770664093453f

#define BLK 256
#define TILE 64                       // items per pipeline stage
#define NS 3                          // pipeline stages
#define NTILES 8                      // tiles per CTA
#define IPC (TILE * NTILES)           // 512 items per CTA
#define GRID (N_ * T_ / IPC)          // 1920 (exact)
#define NSLOT 128

#define SIG_BYTES (TILE * 128)        // 8192
#define MU_BYTES  (TILE * 64)         // 4096
#define X_BYTES   (TILE * 8)          // 512
#define MK_BYTES  (TILE * 4)          // 256
#define STAGE_BYTES (SIG_BYTES + MU_BYTES + X_BYTES + MK_BYTES)  // 13056

// Device-global scratch (zero-init at load; self-reset by the final block).
__device__ float g_accn[T_ * NSLOT];
__device__ float g_accd[T_ * NSLOT];
__device__ unsigned int g_ticket;

struct Stage {                         // 13056 B, all fields 16B-aligned
    float4 sig[TILE * 8];              // 8192: 8 float4 per item
    float2 mu [TILE * 8];              // 4096: 8 float2 per item
    float2 x  [TILE];                  // 512
    float  mk [TILE];                  // 256
};

__device__ __forceinline__ void mbar_init(void* bar, unsigned count) {
    unsigned ba = (unsigned)__cvta_generic_to_shared(bar);
    asm volatile("mbarrier.init.shared.b64 [%0], %1;" :: "r"(ba), "r"(count) : "memory");
}
__device__ __forceinline__ void mbar_expect_tx(void* bar, unsigned bytes) {
    unsigned ba = (unsigned)__cvta_generic_to_shared(bar);
    asm volatile("mbarrier.arrive.expect_tx.shared.b64 _, [%0], %1;"
                 :: "r"(ba), "r"(bytes) : "memory");
}
__device__ __forceinline__ void tma_bulk(void* dst, const void* src, unsigned bytes, void* bar) {
    unsigned d = (unsigned)__cvta_generic_to_shared(dst);
    unsigned b = (unsigned)__cvta_generic_to_shared(bar);
    asm volatile("cp.async.bulk.shared::cluster.global.mbarrier::complete_tx::bytes "
                 "[%0], [%1], %2, [%3];"
                 :: "r"(d), "l"(src), "r"(bytes), "r"(b) : "memory");
}
__device__ __forceinline__ void mbar_wait(void* bar, unsigned parity) {
    unsigned ba = (unsigned)__cvta_generic_to_shared(bar);
    asm volatile(
        "{\n\t"
        ".reg .pred P;\n\t"
        "WAIT_%=:\n\t"
        "mbarrier.try_wait.parity.acquire.cta.shared::cta.b64 P, [%0], %1, 0x989680;\n\t"
        "@!P bra WAIT_%=;\n\t"
        "}" :: "r"(ba), "r"(parity) : "memory");
}
__device__ __forceinline__ void fence_async() {
    asm volatile("fence.proxy.async.shared::cta;" ::: "memory");
}

__global__ __launch_bounds__(BLK) void nll_fused_kernel(
    const float* __restrict__ mu,
    const float* __restrict__ sigma,
    const float* __restrict__ pi,
    const float* __restrict__ x,
    const float* __restrict__ mask,
    float* __restrict__ out)
{
    __shared__ Stage st[NS];
    __shared__ unsigned long long mbar[NS];
    __shared__ float s_num[T_];
    __shared__ float s_den[T_];
    __shared__ unsigned int s_last;

    const int tid = threadIdx.x;
    const int g   = tid >> 3;          // group within block (0..31): one item per pass
    const int m   = tid & 7;           // mixture component
    const int cta_base = blockIdx.x * IPC;

    if (tid < T_) { s_num[tid] = 0.0f; s_den[tid] = 0.0f; }
    if (tid == 0) {
        #pragma unroll
        for (int j = 0; j < NS; j++) mbar_init(&mbar[j], 1);
        fence_async();
    }
    __syncthreads();

    // ---- Prefetch NS tiles ----
    if (tid == 0) {
        #pragma unroll
        for (int j = 0; j < NS; j++) {
            int ib = cta_base + j * TILE;
            mbar_expect_tx(&mbar[j], STAGE_BYTES);
            tma_bulk(st[j].sig, (const char*)sigma + (size_t)ib * 128, SIG_BYTES, &mbar[j]);
            tma_bulk(st[j].mu,  (const char*)mu    + (size_t)ib * 64,  MU_BYTES,  &mbar[j]);
            tma_bulk(st[j].x,   (const char*)x     + (size_t)ib * 8,   X_BYTES,   &mbar[j]);
            tma_bulk(st[j].mk,  (const char*)mask  + (size_t)ib * 4,   MK_BYTES,  &mbar[j]);
        }
    }

    int ph0 = 0, ph1 = 0, ph2 = 0;

    #pragma unroll
    for (int i = 0; i < NTILES; i++) {
        const int s = i % NS;
        const unsigned phase = (s == 0) ? ph0 : (s == 1) ? ph1 : ph2;
        mbar_wait(&mbar[s], phase);

        // ---- Compute: 2 passes x 32 items, 8 lanes per item ----
        #pragma unroll
        for (int p = 0; p < 2; p++) {
            const int l = p * 32 + g;                      // local item in tile
            const int item = cta_base + i * TILE + l;      // item = n*T + t
            const int n = item / T_;
            const int t = item - n * T_;

            float4 s4 = st[s].sig[l * 8 + m];              // conflict-free LDS.128
            float2 m2 = st[s].mu [l * 8 + m];              // conflict-free LDS.64
            float2 xv = st[s].x[l];                        // 8-lane broadcast
            float  pv = __ldg(pi + (size_t)n * M_ + m);    // L2-resident

            float d0 = xv.x - m2.x, d1 = xv.y - m2.y;
            float det  = fmaf(s4.x, s4.w, -s4.y * s4.z);
            float quad = fmaf(d0 * d0, s4.w, fmaf(-2.0f * s4.y, d0 * d1, d1 * d1 * s4.x));
            float lp   = fmaf(-0.5f, quad * __frcp_rn(det),
                              fmaf(-0.5f, __logf(det), -LOG_2PI));

            float a  = lp + pv;
            float mx = a;
            mx = fmaxf(mx, __shfl_xor_sync(0xFFFFFFFFu, mx, 1));
            mx = fmaxf(mx, __shfl_xor_sync(0xFFFFFFFFu, mx, 2));
            mx = fmaxf(mx, __shfl_xor_sync(0xFFFFFFFFu, mx, 4));
            float ea = __expf(a - mx);
            float ep = __expf(pv);        // |pi| small: no max shift needed
            ea += __shfl_xor_sync(0xFFFFFFFFu, ea, 1);
            ep += __shfl_xor_sync(0xFFFFFFFFu, ep, 1);
            ea += __shfl_xor_sync(0xFFFFFFFFu, ea, 2);
            ep += __shfl_xor_sync(0xFFFFFFFFu, ep, 2);
            ea += __shfl_xor_sync(0xFFFFFFFFu, ea, 4);
            ep += __shfl_xor_sync(0xFFFFFFFFu, ep, 4);

            if (m == 0) {
                float mk = st[s].mk[l];
                float loss = -(mx + __logf(ea) - __logf(ep));
                atomicAdd(&s_num[t], loss * mk);
                atomicAdd(&s_den[t], mk);
            }
        }
        __syncthreads();   // everyone done reading stage s

        if (tid == 0 && i + NS < NTILES) {
            int ib = cta_base + (i + NS) * TILE;
            fence_async();
            mbar_expect_tx(&mbar[s], STAGE_BYTES);
            tma_bulk(st[s].sig, (const char*)sigma + (size_t)ib * 128, SIG_BYTES, &mbar[s]);
            tma_bulk(st[s].mu,  (const char*)mu    + (size_t)ib * 64,  MU_BYTES,  &mbar[s]);
            tma_bulk(st[s].x,   (const char*)x     + (size_t)ib * 8,   X_BYTES,   &mbar[s]);
            tma_bulk(st[s].mk,  (const char*)mask  + (size_t)ib * 4,   MK_BYTES,  &mbar[s]);
        }
        if (s == 0) ph0 ^= 1; else if (s == 1) ph1 ^= 1; else ph2 ^= 1;
    }

    // ---- Spread global accumulation (GRID/NSLOT = 15 blocks per address) ----
    const int slot = blockIdx.x & (NSLOT - 1);
    if (tid < T_) {
        atomicAdd(&g_accn[tid * NSLOT + slot], s_num[tid]);
        atomicAdd(&g_accd[tid * NSLOT + slot], s_den[tid]);
    }

    // ---- Last-block finalize (ticket), then self-reset for replay ----
    __threadfence();
    if (tid == 0) s_last = atomicAdd(&g_ticket, 1u);
    __syncthreads();

    if (s_last == (unsigned int)(gridDim.x - 1)) {
        __threadfence();
        double v = 0.0;
        if (tid < T_) {
            const float4* pn = reinterpret_cast<const float4*>(g_accn + tid * NSLOT);
            const float4* pd = reinterpret_cast<const float4*>(g_accd + tid * NSLOT);
            double num = 0.0, den = 0.0;
            #pragma unroll 8
            for (int j = 0; j < NSLOT / 4; j++) {
                float4 a = pn[j];
                float4 b = pd[j];
                num += (double)a.x + (double)a.y + (double)a.z + (double)a.w;
                den += (double)b.x + (double)b.y + (double)b.z + (double)b.w;
            }
            v = num / den;
        }
        #pragma unroll
        for (int off = 16; off > 0; off >>= 1)
            v += __shfl_down_sync(0xFFFFFFFFu, v, off);
        __shared__ double partial[2];
        if (tid == 0)  partial[0] = v;
        if (tid == 32) partial[1] = v;
        __syncthreads();
        if (tid == 0) out[0] = (float)(partial[0] + partial[1]);
        for (int i = tid; i < T_ * NSLOT; i += BLK) {
            g_accn[i] = 0.0f;
            g_accd[i] = 0.0f;
        }
        if (tid == 0) g_ticket = 0u;
    }
}

extern "C" void kernel_launch(void* const* d_in, const int* in_sizes, int n_in,
                              void* d_out, int out_size) {
    const float* mu    = (const float*)d_in[0];
    const float* sigma = (const float*)d_in[1];
    const float* pi    = (const float*)d_in[2];
    const float* x     = (const float*)d_in[3];
    const float* mask  = (const float*)d_in[4];
    float* out = (float*)d_out;

    nll_fused_kernel<<<GRID, BLK>>>(mu, sigma, pi, x, mask, out);
}

// round 16
// speedup vs baseline: 1.4496x; 1.0617x over previous
#include <cuda_runtime.h>
#include <cstdint>

#define N_ 16384
#define T_ 60
#define M_ 8
#define LOG_2PI 1.8378770664093453f
#define QFX 262144.0f            // 2^18 fixed-point scale
#define QFXI (1.0f / 262144.0f)

#define BLK 256
#define TILE 256                 // items per stage (thread-per-item)
#define NS 2                     // stages
#define NTILES 4                 // tiles per CTA
#define IPC (TILE * NTILES)      // 1024
#define GRID (N_ * T_ / IPC)     // 960 (exact)
#define NSLOT 128

#define SIG_BYTES (TILE * 128)   // 32768
#define MU_BYTES  (TILE * 64)    // 16384
#define X_BYTES   (TILE * 8)     // 2048
#define MK_BYTES  (TILE * 4)     // 1024
#define STAGE_BYTES (SIG_BYTES + MU_BYTES + X_BYTES + MK_BYTES)  // 52224
#define SMEM_DYN (NS * STAGE_BYTES)                              // 104448

// Device-global scratch (zero-init at load; self-reset by the final block).
__device__ float g_accn[T_ * NSLOT];
__device__ float g_accd[T_ * NSLOT];
__device__ unsigned int g_ticket;

struct Stage {                    // 52224 B, 16B-aligned fields
    float4 sig[TILE * 8];         // 8 float4 per item
    float2 mu [TILE * 8];         // 8 float2 per item
    float2 x  [TILE];
    float  mk [TILE];
};

__device__ __forceinline__ void mbar_init(void* bar, unsigned count) {
    unsigned ba = (unsigned)__cvta_generic_to_shared(bar);
    asm volatile("mbarrier.init.shared.b64 [%0], %1;" :: "r"(ba), "r"(count) : "memory");
}
__device__ __forceinline__ void mbar_expect_tx(void* bar, unsigned bytes) {
    unsigned ba = (unsigned)__cvta_generic_to_shared(bar);
    asm volatile("mbarrier.arrive.expect_tx.shared.b64 _, [%0], %1;"
                 :: "r"(ba), "r"(bytes) : "memory");
}
__device__ __forceinline__ void tma_bulk(void* dst, const void* src, unsigned bytes, void* bar) {
    unsigned d = (unsigned)__cvta_generic_to_shared(dst);
    unsigned b = (unsigned)__cvta_generic_to_shared(bar);
    asm volatile("cp.async.bulk.shared::cluster.global.mbarrier::complete_tx::bytes "
                 "[%0], [%1], %2, [%3];"
                 :: "r"(d), "l"(src), "r"(bytes), "r"(b) : "memory");
}
__device__ __forceinline__ void mbar_wait(void* bar, unsigned parity) {
    unsigned ba = (unsigned)__cvta_generic_to_shared(bar);
    asm volatile(
        "{\n\t"
        ".reg .pred P;\n\t"
        "WAIT_%=:\n\t"
        "mbarrier.try_wait.parity.acquire.cta.shared::cta.b64 P, [%0], %1, 0x989680;\n\t"
        "@!P bra WAIT_%=;\n\t"
        "}" :: "r"(ba), "r"(parity) : "memory");
}
__device__ __forceinline__ void fence_async() {
    asm volatile("fence.proxy.async.shared::cta;" ::: "memory");
}

__global__ __launch_bounds__(BLK) void nll_fused_kernel(
    const float* __restrict__ mu,
    const float* __restrict__ sigma,
    const float* __restrict__ pi,
    const float* __restrict__ x,
    const float* __restrict__ mask,
    float* __restrict__ out)
{
    extern __shared__ char smem_raw[];
    Stage* st = reinterpret_cast<Stage*>(smem_raw);

    __shared__ unsigned long long mbar[NS];
    __shared__ unsigned long long s_pack[T_];   // Q18: den<<32 | num
    __shared__ unsigned int s_last;

    const int tid = threadIdx.x;
    const int cta_base = blockIdx.x * IPC;

    if (tid < T_) s_pack[tid] = 0ull;
    if (tid == 0) {
        mbar_init(&mbar[0], 1);
        mbar_init(&mbar[1], 1);
        fence_async();
    }
    __syncthreads();

    // ---- Prefetch both stages ----
    if (tid == 0) {
        #pragma unroll
        for (int j = 0; j < NS; j++) {
            int ib = cta_base + j * TILE;
            mbar_expect_tx(&mbar[j], STAGE_BYTES);
            tma_bulk(st[j].sig, (const char*)sigma + (size_t)ib * 128, SIG_BYTES, &mbar[j]);
            tma_bulk(st[j].mu,  (const char*)mu    + (size_t)ib * 64,  MU_BYTES,  &mbar[j]);
            tma_bulk(st[j].x,   (const char*)x     + (size_t)ib * 8,   X_BYTES,   &mbar[j]);
            tma_bulk(st[j].mk,  (const char*)mask  + (size_t)ib * 4,   MK_BYTES,  &mbar[j]);
        }
    }

    const int rot = tid & 7;

    #pragma unroll
    for (int i = 0; i < NTILES; i++) {
        const int s = i & 1;
        mbar_wait(&mbar[s], (i >> 1) & 1);

        const Stage& S = st[s];
        const int item = cta_base + i * TILE + tid;   // item = n*T + t
        const int n = item / T_;
        const int t = item - n * T_;

        float2 xv = S.x[tid];
        const float x0 = xv.x, x1 = xv.y;
        const float4* srow = S.sig + tid * 8;
        const float2* mrow = S.mu  + tid * 8;
        const float*  pin  = pi + (size_t)n * M_;

        float acc = 0.0f, ps = 0.0f;
        #pragma unroll
        for (int cc = 0; cc < 8; cc++) {
            const int c = (cc + rot) & 7;             // rotated: conflict-free LDS
            float4 s4 = srow[c];
            float2 m2 = mrow[c];
            float  pv = __ldg(pin + c);
            float d0 = x0 - m2.x, d1 = x1 - m2.y;
            float det = fmaf(s4.x, s4.w, -s4.y * s4.z);
            float r   = rsqrtf(det);                  // r^2 = 1/det (free rdet)
            float h   = -0.5f * r * r;
            float q   = fmaf(d0 * d0, s4.w, fmaf(-2.0f * s4.y, d0 * d1, d1 * d1 * s4.x));
            acc = fmaf(__expf(fmaf(q, h, pv)), r, acc);
            ps += __expf(pv);
        }
        // loss = LOG_2PI + log(sum exp(pi)) - log(sum term)   (always > 0)
        float mk   = S.mk[tid];
        float loss = LOG_2PI + __logf(ps) - __logf(acc);

        unsigned nfx = __float2uint_rn(loss * mk * QFX);
        unsigned dfx = __float2uint_rn(mk * QFX);
        atomicAdd(&s_pack[t], ((unsigned long long)dfx << 32) | (unsigned long long)nfx);

        __syncthreads();       // all reads of stage s done
        if (tid == 0 && i + NS < NTILES) {
            int ib = cta_base + (i + NS) * TILE;
            fence_async();
            mbar_expect_tx(&mbar[s], STAGE_BYTES);
            tma_bulk(st[s].sig, (const char*)sigma + (size_t)ib * 128, SIG_BYTES, &mbar[s]);
            tma_bulk(st[s].mu,  (const char*)mu    + (size_t)ib * 64,  MU_BYTES,  &mbar[s]);
            tma_bulk(st[s].x,   (const char*)x     + (size_t)ib * 8,   X_BYTES,   &mbar[s]);
            tma_bulk(st[s].mk,  (const char*)mask  + (size_t)ib * 4,   MK_BYTES,  &mbar[s]);
        }
    }

    // ---- Unpack, spread global accumulation ----
    const int slot = blockIdx.x & (NSLOT - 1);
    if (tid < T_) {
        unsigned long long v = s_pack[tid];
        float num = (float)(unsigned)(v & 0xffffffffull) * QFXI;
        float den = (float)(unsigned)(v >> 32) * QFXI;
        atomicAdd(&g_accn[tid * NSLOT + slot], num);
        atomicAdd(&g_accd[tid * NSLOT + slot], den);
    }

    // ---- Last-block finalize (ticket), then self-reset for replay ----
    __threadfence();
    if (tid == 0) s_last = atomicAdd(&g_ticket, 1u);
    __syncthreads();

    if (s_last == (unsigned int)(gridDim.x - 1)) {
        __threadfence();
        double v = 0.0;
        if (tid < T_) {
            const float4* pn = reinterpret_cast<const float4*>(g_accn + tid * NSLOT);
            const float4* pd = reinterpret_cast<const float4*>(g_accd + tid * NSLOT);
            double num = 0.0, den = 0.0;
            #pragma unroll 8
            for (int j = 0; j < NSLOT / 4; j++) {
                float4 a = pn[j];
                float4 b = pd[j];
                num += (double)a.x + (double)a.y + (double)a.z + (double)a.w;
                den += (double)b.x + (double)b.y + (double)b.z + (double)b.w;
            }
            v = num / den;
        }
        #pragma unroll
        for (int off = 16; off > 0; off >>= 1)
            v += __shfl_down_sync(0xFFFFFFFFu, v, off);
        __shared__ double partial[2];
        if (tid == 0)  partial[0] = v;
        if (tid == 32) partial[1] = v;
        __syncthreads();
        if (tid == 0) out[0] = (float)(partial[0] + partial[1]);
        for (int j = tid; j < T_ * NSLOT; j += BLK) {
            g_accn[j] = 0.0f;
            g_accd[j] = 0.0f;
        }
        if (tid == 0) g_ticket = 0u;
    }
}

extern "C" void kernel_launch(void* const* d_in, const int* in_sizes, int n_in,
                              void* d_out, int out_size) {
    const float* mu    = (const float*)d_in[0];
    const float* sigma = (const float*)d_in[1];
    const float* pi    = (const float*)d_in[2];
    const float* x     = (const float*)d_in[3];
    const float* mask  = (const float*)d_in[4];
    float* out = (float*)d_out;

    cudaFuncSetAttribute(nll_fused_kernel,
                         cudaFuncAttributeMaxDynamicSharedMemorySize, SMEM_DYN);
    nll_fused_kernel<<<GRID, BLK, SMEM_DYN>>>(mu, sigma, pi, x, mask, out);
}